// round 1
// baseline (speedup 1.0000x reference)
#include <cuda_runtime.h>
#include <math.h>

#define NN 50000
#define EE 800000
#define F 128
#define OUTC 10
#define GG 64

// ---------------- scratch (device globals; no allocation allowed) ----------
__device__ __align__(16) float g_deg[NN];
__device__ __align__(16) float g_dinv[NN];
__device__ __align__(16) float g_nself[NN];
__device__ __align__(16) int   g_cnt[NN];
__device__ __align__(16) int   g_fill[NN];
__device__ __align__(16) int   g_rowptr[NN + 1];
__device__ __align__(16) int   g_csrc[EE];
__device__ __align__(16) float g_cval[EE];
__device__ __align__(16) float g_h1[NN * F];
__device__ __align__(16) float g_h2[NN * F];
__device__ __align__(16) float g_h3[NN * OUTC];
__device__ __align__(16) float g_h3a[NN * OUTC];
__device__ __align__(16) float g_pool[GG * OUTC];
__device__ __align__(16) float g_pcnt[GG];
__device__ __align__(16) int   g_bsum[256];

// ---------------- init ------------------------------------------------------
__global__ void k_zero() {
    int i = blockIdx.x * blockDim.x + threadIdx.x;
    if (i < NN) { g_deg[i] = 0.f; g_cnt[i] = 0; g_fill[i] = 0; }
    if (i < GG * OUTC) g_pool[i] = 0.f;
    if (i < GG) g_pcnt[i] = 0.f;
}

// degree (weighted, by dst) + in-degree histogram
__global__ void k_deg(const int* __restrict__ ei, const float* __restrict__ ew) {
    int e = blockIdx.x * blockDim.x + threadIdx.x;
    if (e >= EE) return;
    int d = ei[EE + e];
    atomicAdd(&g_deg[d], ew[e]);
    atomicAdd(&g_cnt[d], 1);
}

// dinv = rsqrt(deg + 1)  (self-loop weight 1 always present -> deg+1 >= 1 > 0)
__global__ void k_dinv() {
    int i = blockIdx.x * blockDim.x + threadIdx.x;
    if (i >= NN) return;
    float di = rsqrtf(g_deg[i] + 1.0f);
    g_dinv[i] = di;
    g_nself[i] = di * di;   // self-loop norm: dinv*1*dinv
}

// ---------------- 3-stage exclusive scan of g_cnt -> g_rowptr ---------------
__global__ void k_scan1() {
    __shared__ int s[256];
    int tid = threadIdx.x;
    int i = blockIdx.x * 256 + tid;
    int v = (i < NN) ? g_cnt[i] : 0;
    s[tid] = v; __syncthreads();
#pragma unroll
    for (int off = 1; off < 256; off <<= 1) {
        int t = (tid >= off) ? s[tid - off] : 0;
        __syncthreads();
        s[tid] += t;
        __syncthreads();
    }
    if (i < NN) g_rowptr[i] = s[tid] - v;      // exclusive within block
    if (tid == 255) g_bsum[blockIdx.x] = s[255];
}

__global__ void k_scan2(int nblk) {
    __shared__ int s[256];
    int tid = threadIdx.x;
    int v = (tid < nblk) ? g_bsum[tid] : 0;
    s[tid] = v; __syncthreads();
#pragma unroll
    for (int off = 1; off < 256; off <<= 1) {
        int t = (tid >= off) ? s[tid - off] : 0;
        __syncthreads();
        s[tid] += t;
        __syncthreads();
    }
    if (tid < nblk) g_bsum[tid] = s[tid] - v;  // exclusive block offsets
}

__global__ void k_scan3() {
    int i = blockIdx.x * blockDim.x + threadIdx.x;
    if (i < NN) g_rowptr[i] += g_bsum[i >> 8];
    if (i == 0) g_rowptr[NN] = EE;
}

// scatter edges into per-dst buckets, storing src + norm value
__global__ void k_fill(const int* __restrict__ ei, const float* __restrict__ ew) {
    int e = blockIdx.x * blockDim.x + threadIdx.x;
    if (e >= EE) return;
    int s = ei[e];
    int d = ei[EE + e];
    float nv = g_dinv[s] * ew[e] * g_dinv[d];
    int p = g_rowptr[d] + atomicAdd(&g_fill[d], 1);
    g_csrc[p] = s;
    g_cval[p] = nv;
}

// ---------------- dense GEMM: Y[nr,128] = X[nr,128] @ W[128,128] ------------
__global__ void __launch_bounds__(256) k_gemm128(
    const float* __restrict__ X, const float* __restrict__ W,
    float* __restrict__ Y, int nrows)
{
    extern __shared__ float smem[];
    float* Ws = smem;              // 128*128
    float* Xs = smem + F * F;      // 64*128
    int tid = threadIdx.x;
    // load W (16384 floats)
    for (int i = tid * 4; i < F * F; i += 1024)
        *(float4*)&Ws[i] = *(const float4*)&W[i];
    // load X tile (64 rows)
    int row0 = blockIdx.x * 64;
    for (int i = tid * 4; i < 64 * F; i += 1024) {
        int r = row0 + (i >> 7);
        float4 v = make_float4(0.f, 0.f, 0.f, 0.f);
        if (r < nrows) v = *(const float4*)&X[r * F + (i & 127)];
        *(float4*)&Xs[i] = v;
    }
    __syncthreads();

    int tx = tid & 31;   // 4 cols at tx*4
    int ty = tid >> 5;   // 8 rows at ty*8
    float acc[8][4];
#pragma unroll
    for (int r = 0; r < 8; r++)
#pragma unroll
        for (int c = 0; c < 4; c++) acc[r][c] = 0.f;

#pragma unroll 1
    for (int k = 0; k < F; k += 4) {
        float4 xv[8];
#pragma unroll
        for (int r = 0; r < 8; r++)
            xv[r] = *(float4*)&Xs[(ty * 8 + r) * F + k];
        float4 wv[4];
#pragma unroll
        for (int kk = 0; kk < 4; kk++)
            wv[kk] = *(float4*)&Ws[(k + kk) * F + tx * 4];
#pragma unroll
        for (int r = 0; r < 8; r++) {
            acc[r][0] += xv[r].x * wv[0].x + xv[r].y * wv[1].x + xv[r].z * wv[2].x + xv[r].w * wv[3].x;
            acc[r][1] += xv[r].x * wv[0].y + xv[r].y * wv[1].y + xv[r].z * wv[2].y + xv[r].w * wv[3].y;
            acc[r][2] += xv[r].x * wv[0].z + xv[r].y * wv[1].z + xv[r].z * wv[2].z + xv[r].w * wv[3].z;
            acc[r][3] += xv[r].x * wv[0].w + xv[r].y * wv[1].w + xv[r].z * wv[2].w + xv[r].w * wv[3].w;
        }
    }

#pragma unroll
    for (int r = 0; r < 8; r++) {
        int row = row0 + ty * 8 + r;
        if (row < nrows) {
            float4 v = make_float4(acc[r][0], acc[r][1], acc[r][2], acc[r][3]);
            *(float4*)&Y[row * F + tx * 4] = v;
        }
    }
}

// ---------------- sparse aggregation, 128-wide (warp per node) --------------
__global__ void k_agg128(const float* __restrict__ H, float* __restrict__ O,
                         const float* __restrict__ bias, int do_relu)
{
    int gt = blockIdx.x * blockDim.x + threadIdx.x;
    int node = gt >> 5;
    int lane = gt & 31;
    if (node >= NN) return;
    const float4* H4 = (const float4*)H;

    float4 h = H4[node * 32 + lane];
    float ns = g_nself[node];
    float4 acc = make_float4(ns * h.x, ns * h.y, ns * h.z, ns * h.w);

    int p = g_rowptr[node];
    int p1 = g_rowptr[node + 1];
    int s = 0; float v = 0.f;
    if (p < p1) { s = g_csrc[p]; v = g_cval[p]; }
    while (p < p1) {
        int sn = 0; float vn = 0.f;
        if (p + 1 < p1) { sn = g_csrc[p + 1]; vn = g_cval[p + 1]; }
        float4 hs = H4[s * 32 + lane];
        acc.x += v * hs.x; acc.y += v * hs.y; acc.z += v * hs.z; acc.w += v * hs.w;
        s = sn; v = vn; p++;
    }
    float4 b = ((const float4*)bias)[lane];
    acc.x += b.x; acc.y += b.y; acc.z += b.z; acc.w += b.w;
    if (do_relu) {
        acc.x = fmaxf(acc.x, 0.f); acc.y = fmaxf(acc.y, 0.f);
        acc.z = fmaxf(acc.z, 0.f); acc.w = fmaxf(acc.w, 0.f);
    }
    ((float4*)O)[node * 32 + lane] = acc;
}

// ---------------- output GEMM: h3[n,10] = H[n,128] @ W3[128,10] -------------
__global__ void k_gemm_out(const float* __restrict__ H, const float* __restrict__ W3)
{
    __shared__ __align__(16) float Wt[OUTC * F];  // [c][k]
    int tid = threadIdx.x;
    for (int i = tid; i < OUTC * F; i += blockDim.x) {
        int c = i >> 7, k = i & 127;
        Wt[i] = W3[k * OUTC + c];
    }
    __syncthreads();

    int gt = blockIdx.x * blockDim.x + tid;
    int node = gt >> 5;
    int lane = gt & 31;
    if (node >= NN) return;

    float4 xv = ((const float4*)H)[node * 32 + lane];
    float acc[OUTC];
#pragma unroll
    for (int c = 0; c < OUTC; c++) {
        float4 wv = ((const float4*)Wt)[c * 32 + lane];
        acc[c] = xv.x * wv.x + xv.y * wv.y + xv.z * wv.z + xv.w * wv.w;
    }
#pragma unroll
    for (int off = 16; off; off >>= 1)
#pragma unroll
        for (int c = 0; c < OUTC; c++)
            acc[c] += __shfl_xor_sync(0xffffffffu, acc[c], off);
    if (lane == 0) {
#pragma unroll
        for (int c = 0; c < OUTC; c++) g_h3[node * OUTC + c] = acc[c];
    }
}

// ---------------- sparse aggregation, 10-wide + bias ------------------------
__global__ void k_agg10(const float* __restrict__ b3)
{
    int gt = blockIdx.x * blockDim.x + threadIdx.x;
    int node = gt >> 5;
    int lane = gt & 31;
    if (node >= NN) return;

    float acc = 0.f;
    if (lane < OUTC) acc = g_nself[node] * g_h3[node * OUTC + lane];
    int p = g_rowptr[node];
    int p1 = g_rowptr[node + 1];
    for (; p < p1; p++) {
        int s = g_csrc[p];
        float v = g_cval[p];
        if (lane < OUTC) acc += v * g_h3[s * OUTC + lane];
    }
    if (lane < OUTC) g_h3a[node * OUTC + lane] = acc + b3[lane];
}

// ---------------- pooling: smem-staged segment sums -------------------------
__global__ void k_pool(const int* __restrict__ batch)
{
    __shared__ float sp[GG * OUTC];
    __shared__ float sc[GG];
    int tid = threadIdx.x;
    for (int j = tid; j < GG * OUTC; j += blockDim.x) sp[j] = 0.f;
    for (int j = tid; j < GG; j += blockDim.x) sc[j] = 0.f;
    __syncthreads();

    int i = blockIdx.x * blockDim.x + tid;
    if (i < NN) {
        int g = batch[i];
        atomicAdd(&sc[g], 1.0f);
#pragma unroll
        for (int c = 0; c < OUTC; c++)
            atomicAdd(&sp[g * OUTC + c], g_h3a[i * OUTC + c]);
    }
    __syncthreads();

    for (int j = tid; j < GG * OUTC; j += blockDim.x)
        if (sp[j] != 0.f) atomicAdd(&g_pool[j], sp[j]);
    for (int j = tid; j < GG; j += blockDim.x)
        if (sc[j] != 0.f) atomicAdd(&g_pcnt[j], sc[j]);
}

// ---------------- mean + log_softmax ----------------------------------------
__global__ void k_final(float* __restrict__ out)
{
    int g = threadIdx.x;
    if (g >= GG) return;
    float cnt = fmaxf(g_pcnt[g], 1.0f);
    float v[OUTC];
    float m = -1e30f;
#pragma unroll
    for (int c = 0; c < OUTC; c++) {
        v[c] = g_pool[g * OUTC + c] / cnt;
        m = fmaxf(m, v[c]);
    }
    float s = 0.f;
#pragma unroll
    for (int c = 0; c < OUTC; c++) s += expf(v[c] - m);
    float l = logf(s) + m;
#pragma unroll
    for (int c = 0; c < OUTC; c++) out[g * OUTC + c] = v[c] - l;
}

// ---------------- launch ----------------------------------------------------
extern "C" void kernel_launch(void* const* d_in, const int* in_sizes, int n_in,
                              void* d_out, int out_size)
{
    const float* x     = (const float*)d_in[0];
    const int*   ei    = (const int*)  d_in[1];
    const float* ew    = (const float*)d_in[2];
    const int*   batch = (const int*)  d_in[3];
    const float* W1    = (const float*)d_in[4];
    const float* b1    = (const float*)d_in[5];
    const float* W2    = (const float*)d_in[6];
    const float* b2    = (const float*)d_in[7];
    const float* W3    = (const float*)d_in[8];
    const float* b3    = (const float*)d_in[9];
    float* out = (float*)d_out;

    const int SMEM_GEMM = (F * F + 64 * F) * sizeof(float);   // 96 KB
    cudaFuncSetAttribute(k_gemm128, cudaFuncAttributeMaxDynamicSharedMemorySize, SMEM_GEMM);

    float *h1p, *h2p;
    cudaGetSymbolAddress((void**)&h1p, g_h1);
    cudaGetSymbolAddress((void**)&h2p, g_h2);

    const int nBlkN  = (NN + 255) / 256;          // 196
    const int nBlkE  = (EE + 255) / 256;          // 3125
    const int nBlkW  = (NN * 32 + 255) / 256;     // 6250 (warp-per-node kernels)
    const int nBlkG  = (NN + 63) / 64;            // 782 (gemm128)

    k_zero<<<nBlkN, 256>>>();
    k_deg<<<nBlkE, 256>>>(ei, ew);
    k_dinv<<<nBlkN, 256>>>();
    k_scan1<<<nBlkN, 256>>>();
    k_scan2<<<1, 256>>>(nBlkN);
    k_scan3<<<nBlkN, 256>>>();
    k_fill<<<nBlkE, 256>>>(ei, ew);

    // layer 1: h1 = x@W1 ; h2 = relu(S h1 + b1)
    k_gemm128<<<nBlkG, 256, SMEM_GEMM>>>(x, W1, h1p, NN);
    k_agg128<<<nBlkW, 256>>>(h1p, h2p, b1, 1);

    // layer 2: h1 = h2@W2 ; h2 = relu(S h1 + b2)
    k_gemm128<<<nBlkG, 256, SMEM_GEMM>>>(h2p, W2, h1p, NN);
    k_agg128<<<nBlkW, 256>>>(h1p, h2p, b2, 1);

    // layer 3: h3 = h2@W3 ; h3a = S h3 + b3
    k_gemm_out<<<nBlkW, 256>>>(h2p, W3);
    k_agg10<<<nBlkW, 256>>>(b3);

    // pooling + log_softmax
    k_pool<<<nBlkN, 256>>>(batch);
    k_final<<<1, 64>>>(out);
}